// round 9
// baseline (speedup 1.0000x reference)
#include <cuda_runtime.h>

#define BATCH   32
#define NA      8732
#define NCLASS  91
#define NC      90
#define KTOP    400
#define NCAND   (NC * KTOP)      /* 36000 */
#define MAXDET  200
#define IMGSZ   300.0f
#define SCORE_T 0.01f
#define NMS_T   0.45f
#define BBOX_CLIP 4.135166556742356f   /* log(1000/16) */
#define NEG_INF __int_as_float(0xff800000)

typedef unsigned long long u64;
typedef unsigned u32;

// -------- scratch (device globals; no allocations allowed) --------
__device__ float  d_probs[(size_t)BATCH * NC * NA];      // masked fg scores, class-major
__device__ float4 d_dboxes[(size_t)BATCH * NA];          // decoded boxes (raw)
__device__ float  d_candScore[(size_t)BATCH * NCAND];    // topk scores -> survivor scores
__device__ int    d_candAnchor[(size_t)BATCH * NCAND];   // topk anchor indices
__device__ float4 d_candBox[(size_t)BATCH * NCAND];      // topk boxes WITH class offset

__device__ __forceinline__ u32 fmono(float f) {
    u32 u = __float_as_uint(f);
    return u ^ ((u >> 31) ? 0xFFFFFFFFu : 0x80000000u);
}

// ================= Kernel 1: softmax (XLA:GPU warp row-reduce order) + decode
// FROZEN ARITHMETIC: bitwise-matches the reference lowering. Do not alter.
__global__ void __launch_bounds__(1024) k_softmax_decode(
        const float* __restrict__ logits,
        const float* __restrict__ reg,
        const float* __restrict__ anchors) {
    __shared__ float s_p[NC][33];
    int w = threadIdx.x >> 5, lane = threadIdx.x & 31;
    long flat = (long)blockIdx.x * 32 + w;
    size_t lbase = (size_t)flat * NCLASS;

    float x0 = logits[lbase + lane];
    float x1 = logits[lbase + lane + 32];
    float x2 = (lane < 27) ? logits[lbase + lane + 64] : NEG_INF;

    float m = fmaxf(fmaxf(x0, x1), x2);
    #pragma unroll
    for (int o = 16; o; o >>= 1) m = fmaxf(m, __shfl_down_sync(0xffffffffu, m, o));
    m = __shfl_sync(0xffffffffu, m, 0);

    float e0 = expf(x0 - m), e1 = expf(x1 - m), e2 = expf(x2 - m);
    float s = __fadd_rn(__fadd_rn(e0, e1), e2);
    #pragma unroll
    for (int o = 16; o; o >>= 1) s = __fadd_rn(s, __shfl_down_sync(0xffffffffu, s, o));
    s = __shfl_sync(0xffffffffu, s, 0);

    if (lane >= 1) {
        float p = __fdiv_rn(e0, s);
        s_p[lane - 1][w] = (p > SCORE_T) ? p : NEG_INF;
    }
    {
        float p = __fdiv_rn(e1, s);
        s_p[lane + 31][w] = (p > SCORE_T) ? p : NEG_INF;
    }
    if (lane < 27) {
        float p = __fdiv_rn(e2, s);
        s_p[lane + 63][w] = (p > SCORE_T) ? p : NEG_INF;
    }
    __syncthreads();

    for (int i = threadIdx.x; i < NC * 32; i += 1024) {
        int c = i >> 5, wl = i & 31;
        long fl = (long)blockIdx.x * 32 + wl;
        int b = (int)(fl / NA), a = (int)(fl % NA);
        d_probs[((size_t)b * NC + c) * NA + a] = s_p[c][wl];
    }

    if (threadIdx.x < 32) {
        long fl = (long)blockIdx.x * 32 + threadIdx.x;
        int b = (int)(fl / NA), a = (int)(fl % NA);
        float4 rg = ((const float4*)reg)[fl];
        float4 an = ((const float4*)anchors)[a];
        float wa = __fsub_rn(an.z, an.x), ha = __fsub_rn(an.w, an.y);
        float cxa = __fadd_rn(an.x, __fmul_rn(0.5f, wa));
        float cya = __fadd_rn(an.y, __fmul_rn(0.5f, ha));
        float dx = __fdiv_rn(rg.x, 10.0f), dy = __fdiv_rn(rg.y, 10.0f);
        float dw = fminf(__fdiv_rn(rg.z, 5.0f), BBOX_CLIP);
        float dh = fminf(__fdiv_rn(rg.w, 5.0f), BBOX_CLIP);
        float cx = __fadd_rn(__fmul_rn(dx, wa), cxa);
        float cy = __fadd_rn(__fmul_rn(dy, ha), cya);
        float bw = __fmul_rn(expf(dw), wa), bh = __fmul_rn(expf(dh), ha);
        float hw = __fmul_rn(0.5f, bw), hh = __fmul_rn(0.5f, bh);
        float4 bx;
        bx.x = fminf(fmaxf(__fsub_rn(cx, hw), 0.f), IMGSZ);
        bx.y = fminf(fmaxf(__fsub_rn(cy, hh), 0.f), IMGSZ);
        bx.z = fminf(fmaxf(__fadd_rn(cx, hw), 0.f), IMGSZ);
        bx.w = fminf(fmaxf(__fadd_rn(cy, hh), 0.f), IMGSZ);
        d_dboxes[(size_t)b * NA + a] = bx;
    }
}

// ================= Kernel 2: per-(b,c) top-400 =================
#define TKTHREADS 512
#define NLOC 18
#define TKCAP 512

__global__ void __launch_bounds__(TKTHREADS) k_topk() {
    int b = blockIdx.x / NC, c = blockIdx.x % NC;
    const float* sc = &d_probs[((size_t)b * NC + c) * NA];
    int t = threadIdx.x;

    u32 key[NLOC];
    #pragma unroll
    for (int j = 0; j < NLOC; j++) {
        int idx = j * TKTHREADS + t;
        float v = (idx < NA) ? sc[idx] : -1.0f;
        key[j] = (idx < NA && v > SCORE_T) ? fmono(v) : 0u;
    }

    __shared__ int s_cnt;
    u64 lo = 0xBC23D70Bull, hi = 0xBF800000ull;
    u32 tau = 0;
    while (lo <= hi) {
        u32 mid = (u32)(lo + ((hi - lo) >> 1));
        if (t == 0) s_cnt = 0;
        __syncthreads();
        int cl = 0;
        #pragma unroll
        for (int j = 0; j < NLOC; j++) cl += (key[j] >= mid);
        #pragma unroll
        for (int o = 16; o; o >>= 1) cl += __shfl_down_sync(0xffffffffu, cl, o);
        if ((t & 31) == 0) atomicAdd(&s_cnt, cl);
        __syncthreads();
        int cnt = s_cnt;
        __syncthreads();
        if (cnt >= KTOP) { tau = mid; lo = (u64)mid + 1; }
        else             { hi = (u64)mid - 1; }
    }

    __shared__ u64 buf[TKCAP];
    __shared__ int s_n;
    if (t == 0) s_n = 0;
    if (t < TKCAP) buf[t] = 0ull;
    __syncthreads();
    #pragma unroll
    for (int j = 0; j < NLOC; j++) {
        if (key[j] != 0u && key[j] >= tau) {
            int p = atomicAdd(&s_n, 1);
            if (p < TKCAP) {
                u32 anchor = (u32)(j * TKTHREADS + t);
                buf[p] = ((u64)key[j] << 32) | (u64)(0xFFFFFFFFu - anchor);
            }
        }
    }
    __syncthreads();

    for (int k = 2; k <= TKCAP; k <<= 1) {
        for (int j2 = k >> 1; j2 > 0; j2 >>= 1) {
            int i = t;
            if (i < TKCAP) {
                int ixj = i ^ j2;
                if (ixj > i) {
                    u64 x = buf[i], y = buf[ixj];
                    bool sw = ((i & k) == 0) ? (x < y) : (x > y);
                    if (sw) { buf[i] = y; buf[ixj] = x; }
                }
            }
            __syncthreads();
        }
    }

    int nv = min(s_n, TKCAP);
    size_t obase = (size_t)b * NCAND + (size_t)c * KTOP;
    float off = __fmul_rn((float)(c + 1), IMGSZ + 1.0f);
    if (t < KTOP) {
        float scv = NEG_INF;
        int anc = 0;
        if (t < nv) {
            u64 v = buf[t];
            u32 h32 = (u32)(v >> 32);
            scv = __uint_as_float(h32 ^ 0x80000000u);
            anc = (int)(0xFFFFFFFFu - (u32)v);
        }
        d_candScore[obase + t]  = scv;
        d_candAnchor[obase + t] = anc;
        float4 raw = d_dboxes[(size_t)b * NA + anc];
        float4 ob;
        ob.x = __fadd_rn(raw.x, off);
        ob.y = __fadd_rn(raw.y, off);
        ob.z = __fadd_rn(raw.z, off);
        ob.w = __fadd_rn(raw.w, off);
        d_candBox[obase + t] = ob;
    }
}

// ===== Kernel 3: bitmask greedy NMS (exact; candidates pre-sorted) =====
#define NW 7   /* ceil(400/64) */

__global__ void __launch_bounds__(416) k_nms() {
    int b = blockIdx.x / NC, c = blockIdx.x % NC;
    __shared__ float  s_sc[KTOP];
    __shared__ float4 s_bx[KTOP];
    __shared__ u64    s_mask[KTOP][NW];   // row i: which j>i it would suppress
    __shared__ u64    s_alive[NW];
    __shared__ u64    s_haskill[NW];
    int t = threadIdx.x;
    size_t base = (size_t)b * NCAND + (size_t)c * KTOP;

    if (t < NW) { s_alive[t] = 0ull; s_haskill[t] = 0ull; }
    __syncthreads();

    bool valid = false;
    if (t < KTOP) {
        float s = d_candScore[base + t];
        s_sc[t] = s;
        s_bx[t] = d_candBox[base + t];
        valid = isfinite(s);
        if (valid) atomicOr(&s_alive[t >> 6], 1ull << (t & 63));
    }
    __syncthreads();

    // Phase A: per-row suppression masks (reference IoU math, fdiv gated exact)
    if (t < KTOP) {
        float4 bi = s_bx[t];
        float ai = __fmul_rn(__fsub_rn(bi.z, bi.x), __fsub_rn(bi.w, bi.y));
        u64 any = 0ull;
        #pragma unroll
        for (int w = 0; w < NW; w++) {
            u64 m = 0ull;
            if (valid) {
                int jlo = max(w << 6, t + 1);
                int jhi = min((w << 6) + 64, KTOP);
                for (int j = jlo; j < jhi; j++) {
                    float4 bj = s_bx[j];
                    float aj = __fmul_rn(__fsub_rn(bj.z, bj.x), __fsub_rn(bj.w, bj.y));
                    float lx = fmaxf(bi.x, bj.x), ly = fmaxf(bi.y, bj.y);
                    float rx = fminf(bi.z, bj.z), ry = fminf(bi.w, bj.w);
                    float iw = fmaxf(__fsub_rn(rx, lx), 0.f);
                    float ih = fmaxf(__fsub_rn(ry, ly), 0.f);
                    float inter = __fmul_rn(iw, ih);
                    bool kill = false;
                    if (inter > 0.f) {   // exact: inter==0 -> iou==0 <= T
                        float den = __fadd_rn(__fsub_rn(__fadd_rn(ai, aj), inter), 1e-9f);
                        kill = (__fdiv_rn(inter, den) > NMS_T);
                    }
                    m |= ((u64)kill) << (j & 63);
                }
            }
            s_mask[t][w] = m;
            any |= m;
        }
        if (any) atomicOr(&s_haskill[t >> 6], 1ull << (t & 63));
    }
    __syncthreads();

    // Phase B: serial bitmap walk, skipping non-killing rows via ffs
    if (t == 0) {
        u64 a[NW], hk[NW];
        #pragma unroll
        for (int w = 0; w < NW; w++) { a[w] = s_alive[w]; hk[w] = s_haskill[w]; }
        #pragma unroll
        for (int w = 0; w < NW; w++) {
            u64 rem = hk[w];
            while (rem) {
                int bit = __ffsll((long long)rem) - 1;
                rem &= rem - 1;
                if ((a[w] >> bit) & 1ull) {      // alive at its turn
                    int i = (w << 6) + bit;
                    #pragma unroll
                    for (int u = 0; u < NW; u++) a[u] &= ~s_mask[i][u];
                }
            }
        }
        #pragma unroll
        for (int w = 0; w < NW; w++) s_alive[w] = a[w];
    }
    __syncthreads();

    if (t < KTOP) {
        bool al = (s_alive[t >> 6] >> (t & 63)) & 1ull;
        d_candScore[base + t] = al ? s_sc[t] : NEG_INF;
    }
}

// ===== Kernel 4: global top-200 of survivors by (score desc, idx asc) =====
#define SELCAP 512
#define SELPAD 36864   /* 9216 uint4 */

__global__ void __launch_bounds__(1024) k_select(float* __restrict__ out) {
    extern __shared__ u32 s_key[];        // SELPAD u32 = 144 KB
    __shared__ u64 buf[SELCAP];
    __shared__ int s_cnt, s_n;
    int b = blockIdx.x, t = threadIdx.x;

    for (int i = t; i < NCAND; i += 1024) {
        float v = d_candScore[(size_t)b * NCAND + i];
        s_key[i] = isfinite(v) ? fmono(v) : 0u;
    }
    for (int i = NCAND + t; i < SELPAD; i += 1024) s_key[i] = 0u;
    if (t < SELCAP) buf[t] = 0ull;

    u64 lo = 0xBC23D70Bull, hi = 0xBF800000ull;
    u32 tau = 0;
    const uint4* k4 = (const uint4*)s_key;
    __syncthreads();
    while (lo <= hi) {
        u32 mid = (u32)(lo + ((hi - lo) >> 1));
        if (t == 0) s_cnt = 0;
        __syncthreads();
        int cl = 0;
        #pragma unroll
        for (int k = 0; k < 9; k++) {
            uint4 v = k4[t + (k << 10)];
            cl += (v.x >= mid) + (v.y >= mid) + (v.z >= mid) + (v.w >= mid);
        }
        #pragma unroll
        for (int o = 16; o; o >>= 1) cl += __shfl_down_sync(0xffffffffu, cl, o);
        if ((t & 31) == 0) atomicAdd(&s_cnt, cl);
        __syncthreads();
        int cnt = s_cnt;
        __syncthreads();
        if (cnt >= MAXDET) { tau = mid; lo = (u64)mid + 1; }
        else               { hi = (u64)mid - 1; }
    }
    if (t == 0) s_n = 0;
    __syncthreads();
    #pragma unroll
    for (int k = 0; k < 36; k++) {
        int i = t + (k << 10);
        if (i < NCAND) {
            u32 kv = s_key[i];
            if (kv >= tau) {            // tau > 0 => excludes invalid (0)
                int p = atomicAdd(&s_n, 1);
                if (p < SELCAP)
                    buf[p] = ((u64)kv << 32) | (u64)(0xFFFFFFFFu - (u32)i);
            }
        }
    }
    __syncthreads();

    for (int k = 2; k <= SELCAP; k <<= 1) {
        for (int j2 = k >> 1; j2 > 0; j2 >>= 1) {
            int i = t;
            if (i < SELCAP) {
                int ixj = i ^ j2;
                if (ixj > i) {
                    u64 x = buf[i], y = buf[ixj];
                    bool sw = ((i & k) == 0) ? (x < y) : (x > y);
                    if (sw) { buf[i] = y; buf[ixj] = x; }
                }
            }
            __syncthreads();
        }
    }

    if (t < MAXDET) {
        u64 v = buf[t];
        u32 h = (u32)(v >> 32);
        float4 bx = make_float4(0.f, 0.f, 0.f, 0.f);
        float so = 0.f, lb = 0.f;
        if (h != 0u) {
            int idx = (int)(0xFFFFFFFFu - (u32)v);
            so = __uint_as_float(h ^ 0x80000000u);
            int cls = idx / KTOP;
            int anc = d_candAnchor[(size_t)b * NCAND + idx];
            bx = d_dboxes[(size_t)b * NA + anc];
            lb = (float)(cls + 1);
        }
        size_t ob = ((size_t)b * MAXDET + t) * 4;
        out[ob + 0] = bx.x; out[ob + 1] = bx.y;
        out[ob + 2] = bx.z; out[ob + 3] = bx.w;
        out[(size_t)BATCH * MAXDET * 4 + (size_t)b * MAXDET + t] = so;
        out[(size_t)BATCH * MAXDET * 5 + (size_t)b * MAXDET + t] = lb;
    }
}

// ================= host =================
extern "C" void kernel_launch(void* const* d_in, const int* in_sizes, int n_in,
                              void* d_out, int out_size) {
    const float* logits  = (const float*)d_in[0];
    const float* reg     = (const float*)d_in[1];
    const float* anchors = (const float*)d_in[2];
    float* out = (float*)d_out;

    k_softmax_decode<<<(BATCH * NA) / 32, 1024>>>(logits, reg, anchors);
    k_topk<<<BATCH * NC, TKTHREADS>>>();
    k_nms<<<BATCH * NC, 416>>>();
    cudaFuncSetAttribute(k_select, cudaFuncAttributeMaxDynamicSharedMemorySize,
                         SELPAD * (int)sizeof(u32));
    k_select<<<BATCH, 1024, SELPAD * sizeof(u32)>>>(out);
}

// round 10
// speedup vs baseline: 4.2150x; 4.2150x over previous
#include <cuda_runtime.h>

#define BATCH   32
#define NA      8732
#define NCLASS  91
#define NC      90
#define KTOP    400
#define NCAND   (NC * KTOP)      /* 36000 */
#define MAXDET  200
#define IMGSZ   300.0f
#define SCORE_T 0.01f
#define NMS_T   0.45f
#define BBOX_CLIP 4.135166556742356f
#define NEG_INF __int_as_float(0xff800000)
#define TAU_MIN 0xBC23D70Cu      /* fmono(0.01f)+1 : smallest passing key */

typedef unsigned long long u64;
typedef unsigned u32;

// -------- scratch (device globals; no allocations allowed) --------
__device__ float  d_probs[(size_t)BATCH * NC * NA];
__device__ float4 d_dboxes[(size_t)BATCH * NA];
// fast path
#define SEL_CAP 96
__device__ u64 d_selKey[(size_t)BATCH * NC * SEL_CAP];
__device__ int d_selN[BATCH * NC];
__device__ u32 d_capmax[BATCH];
__device__ int d_overflow[BATCH];
__device__ u64 d_fin[(size_t)BATCH * 9216];
__device__ int d_finN[BATCH];
__device__ int d_ok[BATCH];
// fallback path
__device__ float  d_candScore[(size_t)BATCH * NCAND];
__device__ int    d_candAnchor[(size_t)BATCH * NCAND];
__device__ float4 d_candBox[(size_t)BATCH * NCAND];

__device__ __forceinline__ u32 fmono(float f) {
    u32 u = __float_as_uint(f);
    return u ^ ((u >> 31) ? 0xFFFFFFFFu : 0x80000000u);
}

__global__ void k_init() {
    int t = threadIdx.x;
    if (t < BATCH) {
        d_capmax[t] = 0u; d_overflow[t] = 0; d_finN[t] = 0; d_ok[t] = 0;
    }
}

// ================= Kernel 1: softmax (XLA:GPU warp row-reduce order) + decode
// FROZEN ARITHMETIC: bitwise-matches the reference lowering. Do not alter.
__global__ void __launch_bounds__(1024) k_softmax_decode(
        const float* __restrict__ logits,
        const float* __restrict__ reg,
        const float* __restrict__ anchors) {
    __shared__ float s_p[NC][33];
    int w = threadIdx.x >> 5, lane = threadIdx.x & 31;
    long flat = (long)blockIdx.x * 32 + w;
    size_t lbase = (size_t)flat * NCLASS;

    float x0 = logits[lbase + lane];
    float x1 = logits[lbase + lane + 32];
    float x2 = (lane < 27) ? logits[lbase + lane + 64] : NEG_INF;

    float m = fmaxf(fmaxf(x0, x1), x2);
    #pragma unroll
    for (int o = 16; o; o >>= 1) m = fmaxf(m, __shfl_down_sync(0xffffffffu, m, o));
    m = __shfl_sync(0xffffffffu, m, 0);

    float e0 = expf(x0 - m), e1 = expf(x1 - m), e2 = expf(x2 - m);
    float s = __fadd_rn(__fadd_rn(e0, e1), e2);
    #pragma unroll
    for (int o = 16; o; o >>= 1) s = __fadd_rn(s, __shfl_down_sync(0xffffffffu, s, o));
    s = __shfl_sync(0xffffffffu, s, 0);

    if (lane >= 1) {
        float p = __fdiv_rn(e0, s);
        s_p[lane - 1][w] = (p > SCORE_T) ? p : NEG_INF;
    }
    {
        float p = __fdiv_rn(e1, s);
        s_p[lane + 31][w] = (p > SCORE_T) ? p : NEG_INF;
    }
    if (lane < 27) {
        float p = __fdiv_rn(e2, s);
        s_p[lane + 63][w] = (p > SCORE_T) ? p : NEG_INF;
    }
    __syncthreads();

    for (int i = threadIdx.x; i < NC * 32; i += 1024) {
        int c = i >> 5, wl = i & 31;
        long fl = (long)blockIdx.x * 32 + wl;
        int b = (int)(fl / NA), a = (int)(fl % NA);
        d_probs[((size_t)b * NC + c) * NA + a] = s_p[c][wl];
    }

    if (threadIdx.x < 32) {
        long fl = (long)blockIdx.x * 32 + threadIdx.x;
        int b = (int)(fl / NA), a = (int)(fl % NA);
        float4 rg = ((const float4*)reg)[fl];
        float4 an = ((const float4*)anchors)[a];
        float wa = __fsub_rn(an.z, an.x), ha = __fsub_rn(an.w, an.y);
        float cxa = __fadd_rn(an.x, __fmul_rn(0.5f, wa));
        float cya = __fadd_rn(an.y, __fmul_rn(0.5f, ha));
        float dx = __fdiv_rn(rg.x, 10.0f), dy = __fdiv_rn(rg.y, 10.0f);
        float dw = fminf(__fdiv_rn(rg.z, 5.0f), BBOX_CLIP);
        float dh = fminf(__fdiv_rn(rg.w, 5.0f), BBOX_CLIP);
        float cx = __fadd_rn(__fmul_rn(dx, wa), cxa);
        float cy = __fadd_rn(__fmul_rn(dy, ha), cya);
        float bw = __fmul_rn(expf(dw), wa), bh = __fmul_rn(expf(dh), ha);
        float hw = __fmul_rn(0.5f, bw), hh = __fmul_rn(0.5f, bh);
        float4 bx;
        bx.x = fminf(fmaxf(__fsub_rn(cx, hw), 0.f), IMGSZ);
        bx.y = fminf(fmaxf(__fsub_rn(cy, hh), 0.f), IMGSZ);
        bx.z = fminf(fmaxf(__fadd_rn(cx, hw), 0.f), IMGSZ);
        bx.w = fminf(fmaxf(__fadd_rn(cy, hh), 0.f), IMGSZ);
        d_dboxes[(size_t)b * NA + a] = bx;
    }
}

// ===== Kernel 2: per-(b,c) select all candidates >= tau_c (64..96 pass) =====
#define NLOC 18

__global__ void __launch_bounds__(512) k_selclass() {
    int bc = blockIdx.x;
    int b = bc / NC, c = bc % NC;
    const float* sc = &d_probs[(size_t)bc * NA];
    int t = threadIdx.x;

    u32 key[NLOC];
    #pragma unroll
    for (int j = 0; j < NLOC; j++) {
        int idx = j * 512 + t;
        float v = (idx < NA) ? sc[idx] : -1.0f;
        key[j] = (idx < NA && v > SCORE_T) ? fmono(v) : 0u;
    }

    __shared__ int s_cnt;
    __shared__ int s_n;

    // count all valid (>= TAU_MIN)
    if (t == 0) s_cnt = 0;
    __syncthreads();
    {
        int cl = 0;
        #pragma unroll
        for (int j = 0; j < NLOC; j++) cl += (key[j] >= TAU_MIN);
        #pragma unroll
        for (int o = 16; o; o >>= 1) cl += __shfl_down_sync(0xffffffffu, cl, o);
        if ((t & 31) == 0) atomicAdd(&s_cnt, cl);
    }
    __syncthreads();
    int cnt0 = s_cnt;
    __syncthreads();

    u32 tau = TAU_MIN;
    int capped = 0;
    if (cnt0 > SEL_CAP) {
        capped = 1;
        u64 lo = (u64)TAU_MIN + 1, hi = 0xBF800000ull;
        while (lo <= hi) {
            u32 mid = (u32)(lo + ((hi - lo) >> 1));
            if (t == 0) s_cnt = 0;
            __syncthreads();
            int cl = 0;
            #pragma unroll
            for (int j = 0; j < NLOC; j++) cl += (key[j] >= mid);
            #pragma unroll
            for (int o = 16; o; o >>= 1) cl += __shfl_down_sync(0xffffffffu, cl, o);
            if ((t & 31) == 0) atomicAdd(&s_cnt, cl);
            __syncthreads();
            int cn = s_cnt;
            __syncthreads();
            if (cn >= 64) {
                tau = mid; lo = (u64)mid + 1;
                if (cn <= SEL_CAP) break;
            } else hi = (u64)mid - 1;
        }
    }

    // compact: all keys >= tau (pack key32|~anchor14)
    if (t == 0) s_n = 0;
    __syncthreads();
    #pragma unroll
    for (int j = 0; j < NLOC; j++) {
        if (key[j] >= tau) {
            int p = atomicAdd(&s_n, 1);
            if (p < SEL_CAP) {
                u32 anchor = (u32)(j * 512 + t);
                d_selKey[(size_t)bc * SEL_CAP + p] =
                    ((u64)key[j] << 14) | (u64)(0x3FFFu - anchor);
            }
        }
    }
    __syncthreads();
    if (t == 0) {
        int n = s_n;
        d_selN[bc] = (n < SEL_CAP) ? n : SEL_CAP;
        if (n > SEL_CAP) d_overflow[b] = 1;
        if (capped) atomicMax(&d_capmax[b], tau);
    }
}

// ===== Kernel 3: per-(b,c) sort<=96 + greedy NMS + emit survivor keys =====
__global__ void __launch_bounds__(128) k_nms_fast() {
    int bc = blockIdx.x;
    int b = bc / NC, c = bc % NC;
    int n = d_selN[bc];
    if (n == 0) return;
    int t = threadIdx.x;

    __shared__ u64   s_key[128];
    __shared__ float4 s_bx[SEL_CAP];
    __shared__ float  s_ar[SEL_CAP];
    __shared__ u64   s_m0[SEL_CAP], s_m1[SEL_CAP];
    __shared__ u64   s_alive[2], s_hk[2];

    s_key[t] = (t < n) ? d_selKey[(size_t)bc * SEL_CAP + t] : 0ull;
    if (t < 2) { s_alive[t] = 0ull; s_hk[t] = 0ull; }
    __syncthreads();

    // bitonic sort 128 desc -> greedy order (score desc, anchor asc)
    for (int k = 2; k <= 128; k <<= 1) {
        for (int j2 = k >> 1; j2 > 0; j2 >>= 1) {
            int ixj = t ^ j2;
            if (ixj > t) {
                u64 x = s_key[t], y = s_key[ixj];
                bool sw = ((t & k) == 0) ? (x < y) : (x > y);
                if (sw) { s_key[t] = y; s_key[ixj] = x; }
            }
            __syncthreads();
        }
    }

    u64 v = s_key[t];
    u32 key32 = (u32)(v >> 14);
    int anchor = (int)(0x3FFFu - (u32)(v & 0x3FFF));
    float off = __fmul_rn((float)(c + 1), IMGSZ + 1.0f);
    if (t < n) {
        float4 raw = d_dboxes[(size_t)b * NA + anchor];
        float4 bx;
        bx.x = __fadd_rn(raw.x, off);
        bx.y = __fadd_rn(raw.y, off);
        bx.z = __fadd_rn(raw.z, off);
        bx.w = __fadd_rn(raw.w, off);
        s_bx[t] = bx;
        s_ar[t] = __fmul_rn(__fsub_rn(bx.z, bx.x), __fsub_rn(bx.w, bx.y));
        atomicOr(&s_alive[t >> 6], 1ull << (t & 63));
    }
    __syncthreads();

    // pairwise suppression masks (reference IoU math)
    if (t < n) {
        float4 bi = s_bx[t];
        float ai = s_ar[t];
        u64 m0 = 0ull, m1 = 0ull;
        for (int j = t + 1; j < n; j++) {
            float4 bj = s_bx[j];
            float lx = fmaxf(bi.x, bj.x), ly = fmaxf(bi.y, bj.y);
            float rx = fminf(bi.z, bj.z), ry = fminf(bi.w, bj.w);
            float iw = fmaxf(__fsub_rn(rx, lx), 0.f);
            float ih = fmaxf(__fsub_rn(ry, ly), 0.f);
            float inter = __fmul_rn(iw, ih);
            bool kill = false;
            if (inter > 0.f) {
                float den = __fadd_rn(__fsub_rn(__fadd_rn(ai, s_ar[j]), inter), 1e-9f);
                kill = (__fdiv_rn(inter, den) > NMS_T);
            }
            if (j < 64) m0 |= ((u64)kill) << j;
            else        m1 |= ((u64)kill) << (j - 64);
        }
        s_m0[t] = m0; s_m1[t] = m1;
        if (m0 | m1) atomicOr(&s_hk[t >> 6], 1ull << (t & 63));
    }
    __syncthreads();

    if (t == 0) {
        u64 a0 = s_alive[0], a1 = s_alive[1];
        #pragma unroll
        for (int w = 0; w < 2; w++) {
            u64 rem = s_hk[w];
            while (rem) {
                int bit = __ffsll((long long)rem) - 1;
                rem &= rem - 1;
                u64 ab = (w == 0) ? a0 : a1;
                if ((ab >> bit) & 1ull) {
                    int i = (w << 6) + bit;
                    a0 &= ~s_m0[i]; a1 &= ~s_m1[i];
                }
            }
        }
        s_alive[0] = a0; s_alive[1] = a1;
    }
    __syncthreads();

    if (t < n) {
        bool al = (s_alive[t >> 6] >> (t & 63)) & 1ull;
        if (al) {
            u64 fk = ((u64)key32 << 21) | ((u64)(0x7Fu - (u32)c) << 14)
                   | (u64)(0x3FFFu - (u32)anchor);
            int p = atomicAdd(&d_finN[b], 1);
            d_fin[(size_t)b * 9216 + p] = fk;
        }
    }
}

// ===== Kernel 4: per-image final top-200 (score desc, cls asc, anchor asc) =====
__global__ void __launch_bounds__(1024) k_out_fast(float* __restrict__ out) {
    extern __shared__ u64 s_f[];          // 9216 u64 = 72 KB
    __shared__ u64 buf[512];
    __shared__ int s_cnt, s_n, s_okflag;
    __shared__ u32 s_s200;
    int b = blockIdx.x, t = threadIdx.x;
    int n = d_finN[b];

    #pragma unroll
    for (int k = 0; k < 9; k++) {
        int i = t + (k << 10);
        s_f[i] = (i < n) ? d_fin[(size_t)b * 9216 + i] : 0ull;
    }
    if (t < 512) buf[t] = 0ull;
    __syncthreads();

    // threshold on score part: count in [200, 448]
    u32 tau = TAU_MIN;
    int ovf = d_overflow[b];
    if (n > 448) {
        u64 lo = (u64)TAU_MIN + 1, hi = 0xBF800000ull;
        int cntb = n;
        while (lo <= hi) {
            u32 mid = (u32)(lo + ((hi - lo) >> 1));
            if (t == 0) s_cnt = 0;
            __syncthreads();
            int cl = 0;
            #pragma unroll
            for (int k = 0; k < 9; k++)
                cl += ((u32)(s_f[t + (k << 10)] >> 21) >= mid);
            #pragma unroll
            for (int o = 16; o; o >>= 1) cl += __shfl_down_sync(0xffffffffu, cl, o);
            if ((t & 31) == 0) atomicAdd(&s_cnt, cl);
            __syncthreads();
            int cn = s_cnt;
            __syncthreads();
            if (cn >= MAXDET) {
                tau = mid; cntb = cn; lo = (u64)mid + 1;
                if (cn <= 448) break;
            } else hi = (u64)mid - 1;
        }
        if (cntb > 448) ovf = 1;
    }

    if (t == 0) s_n = 0;
    __syncthreads();
    #pragma unroll
    for (int k = 0; k < 9; k++) {
        u64 v = s_f[t + (k << 10)];
        if (v != 0ull && (u32)(v >> 21) >= tau) {
            int p = atomicAdd(&s_n, 1);
            if (p < 512) buf[p] = v;
        }
    }
    __syncthreads();

    // bitonic 512 desc on full key -> exact reference order
    for (int k = 2; k <= 512; k <<= 1) {
        for (int j2 = k >> 1; j2 > 0; j2 >>= 1) {
            if (t < 512) {
                int ixj = t ^ j2;
                if (ixj > t) {
                    u64 x = buf[t], y = buf[ixj];
                    bool sw = ((t & k) == 0) ? (x < y) : (x > y);
                    if (sw) { buf[t] = y; buf[ixj] = x; }
                }
            }
            __syncthreads();
        }
    }

    if (t == 0) {
        u64 v199 = buf[MAXDET - 1];
        s_s200 = (u32)(v199 >> 21);     // 0 if fewer than 200 survivors
        u32 cm = d_capmax[b];
        int ok = (!ovf) && (cm == 0u || s_s200 > cm);
        s_okflag = ok;
        d_ok[b] = ok;
    }
    __syncthreads();

    if (s_okflag && t < MAXDET) {
        u64 v = buf[t];
        float4 bx = make_float4(0.f, 0.f, 0.f, 0.f);
        float so = 0.f, lb = 0.f;
        if (v != 0ull) {
            u32 key32 = (u32)(v >> 21);
            int cls = (int)(0x7Fu - ((u32)(v >> 14) & 0x7Fu));
            int anchor = (int)(0x3FFFu - (u32)(v & 0x3FFF));
            so = __uint_as_float(key32 ^ 0x80000000u);
            bx = d_dboxes[(size_t)b * NA + anchor];
            lb = (float)(cls + 1);
        }
        size_t ob = ((size_t)b * MAXDET + t) * 4;
        out[ob + 0] = bx.x; out[ob + 1] = bx.y;
        out[ob + 2] = bx.z; out[ob + 3] = bx.w;
        out[(size_t)BATCH * MAXDET * 4 + (size_t)b * MAXDET + t] = so;
        out[(size_t)BATCH * MAXDET * 5 + (size_t)b * MAXDET + t] = lb;
    }
}

// ================= FALLBACK (round-8 proven path, gated on !d_ok[b]) =======
#define TKTHREADS 512
#define TKCAP 512

__global__ void __launch_bounds__(TKTHREADS) k_topk_fb() {
    int b = blockIdx.x / NC, c = blockIdx.x % NC;
    if (d_ok[b]) return;
    const float* sc = &d_probs[((size_t)b * NC + c) * NA];
    int t = threadIdx.x;

    u32 key[NLOC];
    #pragma unroll
    for (int j = 0; j < NLOC; j++) {
        int idx = j * TKTHREADS + t;
        float v = (idx < NA) ? sc[idx] : -1.0f;
        key[j] = (idx < NA && v > SCORE_T) ? fmono(v) : 0u;
    }

    __shared__ int s_cnt;
    u64 lo = 0xBC23D70Bull, hi = 0xBF800000ull;
    u32 tau = 0;
    while (lo <= hi) {
        u32 mid = (u32)(lo + ((hi - lo) >> 1));
        if (t == 0) s_cnt = 0;
        __syncthreads();
        int cl = 0;
        #pragma unroll
        for (int j = 0; j < NLOC; j++) cl += (key[j] >= mid);
        #pragma unroll
        for (int o = 16; o; o >>= 1) cl += __shfl_down_sync(0xffffffffu, cl, o);
        if ((t & 31) == 0) atomicAdd(&s_cnt, cl);
        __syncthreads();
        int cnt = s_cnt;
        __syncthreads();
        if (cnt >= KTOP) { tau = mid; lo = (u64)mid + 1; }
        else             { hi = (u64)mid - 1; }
    }

    __shared__ u64 buf[TKCAP];
    __shared__ int s_n;
    if (t == 0) s_n = 0;
    if (t < TKCAP) buf[t] = 0ull;
    __syncthreads();
    #pragma unroll
    for (int j = 0; j < NLOC; j++) {
        if (key[j] != 0u && key[j] >= tau) {
            int p = atomicAdd(&s_n, 1);
            if (p < TKCAP) {
                u32 anchor = (u32)(j * TKTHREADS + t);
                buf[p] = ((u64)key[j] << 32) | (u64)(0xFFFFFFFFu - anchor);
            }
        }
    }
    __syncthreads();

    for (int k = 2; k <= TKCAP; k <<= 1) {
        for (int j2 = k >> 1; j2 > 0; j2 >>= 1) {
            if (t < TKCAP) {
                int ixj = t ^ j2;
                if (ixj > t) {
                    u64 x = buf[t], y = buf[ixj];
                    bool sw = ((t & k) == 0) ? (x < y) : (x > y);
                    if (sw) { buf[t] = y; buf[ixj] = x; }
                }
            }
            __syncthreads();
        }
    }

    int nv = min(s_n, TKCAP);
    size_t obase = (size_t)b * NCAND + (size_t)c * KTOP;
    float off = __fmul_rn((float)(c + 1), IMGSZ + 1.0f);
    if (t < KTOP) {
        float scv = NEG_INF;
        int anc = 0;
        if (t < nv) {
            u64 v = buf[t];
            u32 h32 = (u32)(v >> 32);
            scv = __uint_as_float(h32 ^ 0x80000000u);
            anc = (int)(0xFFFFFFFFu - (u32)v);
        }
        d_candScore[obase + t]  = scv;
        d_candAnchor[obase + t] = anc;
        float4 raw = d_dboxes[(size_t)b * NA + anc];
        float4 ob;
        ob.x = __fadd_rn(raw.x, off);
        ob.y = __fadd_rn(raw.y, off);
        ob.z = __fadd_rn(raw.z, off);
        ob.w = __fadd_rn(raw.w, off);
        d_candBox[obase + t] = ob;
    }
}

__global__ void __launch_bounds__(416) k_nms_fb() {
    int b = blockIdx.x / NC, c = blockIdx.x % NC;
    if (d_ok[b]) return;
    __shared__ float  s_sc[KTOP];
    __shared__ float4 s_bx[KTOP];
    __shared__ float  s_ar[KTOP];
    __shared__ int    s_alive[KTOP];
    int t = threadIdx.x;
    size_t base = (size_t)b * NCAND + (size_t)c * KTOP;

    float4 my = make_float4(0.f, 0.f, 0.f, 0.f);
    float mya = 0.f;
    if (t < KTOP) {
        float s = d_candScore[base + t];
        float4 bx = d_candBox[base + t];
        s_sc[t] = s;
        s_bx[t] = bx;
        float ar = __fmul_rn(__fsub_rn(bx.z, bx.x), __fsub_rn(bx.w, bx.y));
        s_ar[t] = ar;
        s_alive[t] = isfinite(s) ? 1 : 0;
        my = bx; mya = ar;
    }
    __syncthreads();

    for (int i = 0; i < KTOP; i++) {
        if (s_alive[i]) {
            if (t > i && t < KTOP && s_alive[t]) {
                float4 bi = s_bx[i];
                float lx = fmaxf(bi.x, my.x), ly = fmaxf(bi.y, my.y);
                float rx = fminf(bi.z, my.z), ry = fminf(bi.w, my.w);
                float iw = fmaxf(__fsub_rn(rx, lx), 0.f);
                float ih = fmaxf(__fsub_rn(ry, ly), 0.f);
                float inter = __fmul_rn(iw, ih);
                float den = __fadd_rn(__fsub_rn(__fadd_rn(s_ar[i], mya), inter), 1e-9f);
                float iou = __fdiv_rn(inter, den);
                if (iou > NMS_T) s_alive[t] = 0;
            }
            __syncthreads();
        }
    }
    __syncthreads();
    if (t < KTOP)
        d_candScore[base + t] = s_alive[t] ? s_sc[t] : NEG_INF;
}

#define SELPAD 36864
__global__ void __launch_bounds__(1024) k_select_fb(float* __restrict__ out) {
    int b = blockIdx.x, t = threadIdx.x;
    if (d_ok[b]) return;
    extern __shared__ u32 s_key[];
    __shared__ u64 buf[512];
    __shared__ int s_cnt, s_n;

    for (int i = t; i < NCAND; i += 1024) {
        float v = d_candScore[(size_t)b * NCAND + i];
        s_key[i] = isfinite(v) ? fmono(v) : 0u;
    }
    for (int i = NCAND + t; i < SELPAD; i += 1024) s_key[i] = 0u;
    if (t < 512) buf[t] = 0ull;

    u64 lo = 0xBC23D70Bull, hi = 0xBF800000ull;
    u32 tau = 0;
    const uint4* k4 = (const uint4*)s_key;
    __syncthreads();
    while (lo <= hi) {
        u32 mid = (u32)(lo + ((hi - lo) >> 1));
        if (t == 0) s_cnt = 0;
        __syncthreads();
        int cl = 0;
        #pragma unroll
        for (int k = 0; k < 9; k++) {
            uint4 v = k4[t + (k << 10)];
            cl += (v.x >= mid) + (v.y >= mid) + (v.z >= mid) + (v.w >= mid);
        }
        #pragma unroll
        for (int o = 16; o; o >>= 1) cl += __shfl_down_sync(0xffffffffu, cl, o);
        if ((t & 31) == 0) atomicAdd(&s_cnt, cl);
        __syncthreads();
        int cnt = s_cnt;
        __syncthreads();
        if (cnt >= MAXDET) { tau = mid; lo = (u64)mid + 1; }
        else               { hi = (u64)mid - 1; }
    }
    if (t == 0) s_n = 0;
    __syncthreads();
    #pragma unroll
    for (int k = 0; k < 36; k++) {
        int i = t + (k << 10);
        if (i < NCAND) {
            u32 kv = s_key[i];
            if (kv >= tau) {
                int p = atomicAdd(&s_n, 1);
                if (p < 512)
                    buf[p] = ((u64)kv << 32) | (u64)(0xFFFFFFFFu - (u32)i);
            }
        }
    }
    __syncthreads();

    for (int k = 2; k <= 512; k <<= 1) {
        for (int j2 = k >> 1; j2 > 0; j2 >>= 1) {
            if (t < 512) {
                int ixj = t ^ j2;
                if (ixj > t) {
                    u64 x = buf[t], y = buf[ixj];
                    bool sw = ((t & k) == 0) ? (x < y) : (x > y);
                    if (sw) { buf[t] = y; buf[ixj] = x; }
                }
            }
            __syncthreads();
        }
    }

    if (t < MAXDET) {
        u64 v = buf[t];
        u32 h = (u32)(v >> 32);
        float4 bx = make_float4(0.f, 0.f, 0.f, 0.f);
        float so = 0.f, lb = 0.f;
        if (h != 0u) {
            int idx = (int)(0xFFFFFFFFu - (u32)v);
            so = __uint_as_float(h ^ 0x80000000u);
            int cls = idx / KTOP;
            int anc = d_candAnchor[(size_t)b * NCAND + idx];
            bx = d_dboxes[(size_t)b * NA + anc];
            lb = (float)(cls + 1);
        }
        size_t ob = ((size_t)b * MAXDET + t) * 4;
        out[ob + 0] = bx.x; out[ob + 1] = bx.y;
        out[ob + 2] = bx.z; out[ob + 3] = bx.w;
        out[(size_t)BATCH * MAXDET * 4 + (size_t)b * MAXDET + t] = so;
        out[(size_t)BATCH * MAXDET * 5 + (size_t)b * MAXDET + t] = lb;
    }
}

// ================= host =================
extern "C" void kernel_launch(void* const* d_in, const int* in_sizes, int n_in,
                              void* d_out, int out_size) {
    const float* logits  = (const float*)d_in[0];
    const float* reg     = (const float*)d_in[1];
    const float* anchors = (const float*)d_in[2];
    float* out = (float*)d_out;

    k_init<<<1, 32>>>();
    k_softmax_decode<<<(BATCH * NA) / 32, 1024>>>(logits, reg, anchors);
    k_selclass<<<BATCH * NC, 512>>>();
    k_nms_fast<<<BATCH * NC, 128>>>();
    cudaFuncSetAttribute(k_out_fast, cudaFuncAttributeMaxDynamicSharedMemorySize,
                         9216 * (int)sizeof(u64));
    k_out_fast<<<BATCH, 1024, 9216 * sizeof(u64)>>>(out);
    // fallback chain (no-ops when fast path verified exact)
    k_topk_fb<<<BATCH * NC, TKTHREADS>>>();
    k_nms_fb<<<BATCH * NC, 416>>>();
    cudaFuncSetAttribute(k_select_fb, cudaFuncAttributeMaxDynamicSharedMemorySize,
                         SELPAD * (int)sizeof(u32));
    k_select_fb<<<BATCH, 1024, SELPAD * sizeof(u32)>>>(out);
}